// round 1
// baseline (speedup 1.0000x reference)
#include <cuda_runtime.h>
#include <math.h>

#define HEADS 16
#define DH    64
#define BATCH 8
#define SEQ   512
#define DMODEL 1024
#define INNER 1024            // HEADS*DH
#define QKV_N 3072            // 3*INNER
#define NTOK  4096            // BATCH*SEQ

// Scratch (device globals: allocation-free, graph-capture safe)
__device__ float g_qkv[(size_t)NTOK * QKV_N];            // 48 MB  [tok, 3*inner]
__device__ float g_dots[(size_t)BATCH * HEADS * SEQ * SEQ]; // 128 MB [b,h,i,j] (in-place softmax/mix/ln)
__device__ float g_av[(size_t)NTOK * INNER];             // 16 MB  [tok, inner]

// ---------------------------------------------------------------------------
// Generic tiled fp32 SGEMM: C[M,N] = A[M,K] @ B[K,N] (+ bias). Row-major.
// BM=128 BN=128 BK=16, 256 threads, 8x8 per thread. Dims assumed tile-exact.
// ---------------------------------------------------------------------------
template <bool BIAS>
__global__ void __launch_bounds__(256) sgemm_kernel(
    const float* __restrict__ A, const float* __restrict__ Bm,
    const float* __restrict__ bias, float* __restrict__ C,
    int M, int Ncols, int K)
{
    constexpr int BM = 128, BN = 128, BK = 16, TM = 8, TN = 8;
    __shared__ float As[BK][BM + 4];
    __shared__ float Bs[BK][BN + 4];

    const int tid  = threadIdx.x;
    const int tx   = tid & 15;       // 0..15
    const int ty   = tid >> 4;       // 0..15
    const int row0 = blockIdx.y * BM;
    const int col0 = blockIdx.x * BN;

    float acc[TM][TN] = {};

    const int aRow = tid >> 2;       // tid / (BK/4), 0..63
    const int aCol = tid & 3;        // float4 col within BK
    const int bRow = tid >> 5;       // tid / (BN/4), 0..7
    const int bCol = tid & 31;       // float4 col within BN

    for (int k0 = 0; k0 < K; k0 += BK) {
        #pragma unroll
        for (int p = 0; p < 2; p++) {
            int r = aRow + p * 64;
            float4 v = *reinterpret_cast<const float4*>(
                &A[(size_t)(row0 + r) * K + k0 + aCol * 4]);
            As[aCol * 4 + 0][r] = v.x;
            As[aCol * 4 + 1][r] = v.y;
            As[aCol * 4 + 2][r] = v.z;
            As[aCol * 4 + 3][r] = v.w;
        }
        #pragma unroll
        for (int p = 0; p < 2; p++) {
            int r = bRow + p * 8;
            float4 v = *reinterpret_cast<const float4*>(
                &Bm[(size_t)(k0 + r) * Ncols + col0 + bCol * 4]);
            *reinterpret_cast<float4*>(&Bs[r][bCol * 4]) = v;
        }
        __syncthreads();

        #pragma unroll
        for (int k = 0; k < BK; k++) {
            float ra[TM], rb[TN];
            float4 a0 = *reinterpret_cast<const float4*>(&As[k][ty * TM]);
            float4 a1 = *reinterpret_cast<const float4*>(&As[k][ty * TM + 4]);
            ra[0]=a0.x; ra[1]=a0.y; ra[2]=a0.z; ra[3]=a0.w;
            ra[4]=a1.x; ra[5]=a1.y; ra[6]=a1.z; ra[7]=a1.w;
            float4 b0 = *reinterpret_cast<const float4*>(&Bs[k][tx * TN]);
            float4 b1 = *reinterpret_cast<const float4*>(&Bs[k][tx * TN + 4]);
            rb[0]=b0.x; rb[1]=b0.y; rb[2]=b0.z; rb[3]=b0.w;
            rb[4]=b1.x; rb[5]=b1.y; rb[6]=b1.z; rb[7]=b1.w;
            #pragma unroll
            for (int m = 0; m < TM; m++)
                #pragma unroll
                for (int n = 0; n < TN; n++)
                    acc[m][n] = fmaf(ra[m], rb[n], acc[m][n]);
        }
        __syncthreads();
    }

    #pragma unroll
    for (int m = 0; m < TM; m++) {
        int r = row0 + ty * TM + m;
        #pragma unroll
        for (int n = 0; n < TN; n += 4) {
            int c = col0 + tx * TN + n;
            float4 v;
            v.x = acc[m][n + 0]; v.y = acc[m][n + 1];
            v.z = acc[m][n + 2]; v.w = acc[m][n + 3];
            if (BIAS) {
                v.x += bias[c + 0]; v.y += bias[c + 1];
                v.z += bias[c + 2]; v.w += bias[c + 3];
            }
            *reinterpret_cast<float4*>(&C[(size_t)r * Ncols + c]) = v;
        }
    }
}

// ---------------------------------------------------------------------------
// dots[b,h,i,j] = scale * sum_d Q[b,h,i,d] * K[b,h,j,d]
// Q/K live inside g_qkv: q at offset h*64, k at offset INNER + h*64 per token.
// 64x64 output tile per block, full K=64 in smem.
// ---------------------------------------------------------------------------
__global__ void __launch_bounds__(256) dots_kernel(
    const float* __restrict__ qkv, float* __restrict__ dots)
{
    const int bh = blockIdx.z;                 // 0..127
    const int b  = bh >> 4;
    const int h  = bh & 15;
    const int i0 = blockIdx.y * 64;
    const int j0 = blockIdx.x * 64;

    __shared__ float Qs[64][65];   // [d][i]
    __shared__ float Ks[64][65];   // [d][j]

    const int tid = threadIdx.x;
    const size_t qbase = (size_t)b * SEQ * QKV_N + (size_t)h * DH;

    #pragma unroll
    for (int t = 0; t < 4; t++) {
        int idx = tid + t * 256;    // 0..1023
        int r   = idx >> 4;         // row 0..63
        int c4  = idx & 15;         // float4 col 0..15
        float4 q = *reinterpret_cast<const float4*>(
            &qkv[qbase + (size_t)(i0 + r) * QKV_N + c4 * 4]);
        Qs[c4 * 4 + 0][r] = q.x; Qs[c4 * 4 + 1][r] = q.y;
        Qs[c4 * 4 + 2][r] = q.z; Qs[c4 * 4 + 3][r] = q.w;
        float4 k = *reinterpret_cast<const float4*>(
            &qkv[qbase + INNER + (size_t)(j0 + r) * QKV_N + c4 * 4]);
        Ks[c4 * 4 + 0][r] = k.x; Ks[c4 * 4 + 1][r] = k.y;
        Ks[c4 * 4 + 2][r] = k.z; Ks[c4 * 4 + 3][r] = k.w;
    }
    __syncthreads();

    const int tx = tid & 15, ty = tid >> 4;
    float acc[4][4] = {};
    #pragma unroll
    for (int d = 0; d < 64; d++) {
        float rq[4], rk[4];
        #pragma unroll
        for (int m = 0; m < 4; m++) rq[m] = Qs[d][ty * 4 + m];
        #pragma unroll
        for (int n = 0; n < 4; n++) rk[n] = Ks[d][tx * 4 + n];
        #pragma unroll
        for (int m = 0; m < 4; m++)
            #pragma unroll
            for (int n = 0; n < 4; n++)
                acc[m][n] = fmaf(rq[m], rk[n], acc[m][n]);
    }

    const float scale = 0.125f;    // dh^-0.5 = 1/8
    const size_t obase = ((size_t)bh * SEQ + i0) * SEQ + j0;
    #pragma unroll
    for (int m = 0; m < 4; m++) {
        float4 v;
        v.x = acc[m][0] * scale; v.y = acc[m][1] * scale;
        v.z = acc[m][2] * scale; v.w = acc[m][3] * scale;
        *reinterpret_cast<float4*>(
            &dots[obase + (size_t)(ty * 4 + m) * SEQ + tx * 4]) = v;
    }
}

// ---------------------------------------------------------------------------
// Fused: per (b,i) — softmax over j per head, 16x16 head mix, LayerNorm over
// heads, gamma/beta. In-place on g_dots (block owns full (b,i,:,:) slice and
// reads everything into smem before writing).
// ---------------------------------------------------------------------------
__global__ void __launch_bounds__(256) softmax_mix_ln_kernel(
    float* __restrict__ dots, const float* __restrict__ W,
    const float* __restrict__ gamma, const float* __restrict__ beta)
{
    const int bi = blockIdx.x;       // 0..4095
    const int b  = bi >> 9;
    const int i  = bi & 511;

    __shared__ float sc[HEADS][SEQ];       // 32 KB
    __shared__ float wmat[HEADS][HEADS];
    __shared__ float sg[HEADS], sb[HEADS];

    const int tid = threadIdx.x;
    wmat[tid >> 4][tid & 15] = W[tid];     // 256 threads == 256 weights
    if (tid < HEADS) { sg[tid] = gamma[tid]; sb[tid] = beta[tid]; }

    // Load all 16 head rows (float4)
    #pragma unroll
    for (int t = 0; t < 8; t++) {
        int idx = tid + t * 256;           // float4 index 0..2047
        int h   = idx >> 7;
        int j4  = idx & 127;
        float4 v = *reinterpret_cast<const float4*>(
            &dots[((size_t)(b * HEADS + h) * SEQ + i) * SEQ + j4 * 4]);
        *reinterpret_cast<float4*>(&sc[h][j4 * 4]) = v;
    }
    __syncthreads();

    // Softmax per head: warp w handles heads 2w, 2w+1
    const int warp = tid >> 5, lane = tid & 31;
    #pragma unroll
    for (int hh = 0; hh < 2; hh++) {
        int h = warp * 2 + hh;
        float mx = -1e30f;
        for (int j = lane; j < SEQ; j += 32) mx = fmaxf(mx, sc[h][j]);
        #pragma unroll
        for (int o = 16; o > 0; o >>= 1)
            mx = fmaxf(mx, __shfl_xor_sync(0xffffffffu, mx, o));
        float s = 0.f;
        for (int j = lane; j < SEQ; j += 32) {
            float e = __expf(sc[h][j] - mx);
            sc[h][j] = e;
            s += e;
        }
        #pragma unroll
        for (int o = 16; o > 0; o >>= 1)
            s += __shfl_xor_sync(0xffffffffu, s, o);
        float inv = 1.f / s;
        for (int j = lane; j < SEQ; j += 32) sc[h][j] *= inv;
    }
    __syncthreads();

    // Head mix + LayerNorm over heads, write back in place
    for (int j = tid; j < SEQ; j += 256) {
        float a[HEADS];
        #pragma unroll
        for (int h = 0; h < HEADS; h++) a[h] = sc[h][j];
        float mixed[HEADS];
        #pragma unroll
        for (int g = 0; g < HEADS; g++) {
            float s = 0.f;
            #pragma unroll
            for (int h = 0; h < HEADS; h++) s = fmaf(a[h], wmat[h][g], s);
            mixed[g] = s;
        }
        float mean = 0.f;
        #pragma unroll
        for (int g = 0; g < HEADS; g++) mean += mixed[g];
        mean *= (1.f / HEADS);
        float var = 0.f;
        #pragma unroll
        for (int g = 0; g < HEADS; g++) {
            float d = mixed[g] - mean;
            var = fmaf(d, d, var);
        }
        var *= (1.f / HEADS);
        float inv = rsqrtf(var + 1e-3f);
        #pragma unroll
        for (int g = 0; g < HEADS; g++) {
            float y = (mixed[g] - mean) * inv * sg[g] + sb[g];
            dots[((size_t)(b * HEADS + g) * SEQ + i) * SEQ + j] = y;
        }
    }
}

// ---------------------------------------------------------------------------
// AV: out[b, i, h*64+d] = sum_j attn[b,h,i,j] * V[b,h,j,d]
// V lives in g_qkv at offset 2*INNER + h*64 per token. 64 rows per block.
// ---------------------------------------------------------------------------
__global__ void __launch_bounds__(256) av_kernel(
    const float* __restrict__ attn, const float* __restrict__ qkv,
    float* __restrict__ out)
{
    const int bh = blockIdx.y;
    const int b  = bh >> 4;
    const int h  = bh & 15;
    const int i0 = blockIdx.x * 64;

    __shared__ float Ps[32][68];   // [k][i]
    __shared__ float Vs[32][68];   // [k][d]

    const int tid = threadIdx.x;
    const int tx = tid & 15, ty = tid >> 4;
    float acc[4][4] = {};

    const size_t pbase = ((size_t)bh * SEQ + i0) * SEQ;
    const size_t vbase = (size_t)b * SEQ * QKV_N + 2 * INNER + (size_t)h * DH;

    for (int k0 = 0; k0 < SEQ; k0 += 32) {
        #pragma unroll
        for (int t = 0; t < 2; t++) {
            int idx = tid + t * 256;       // 0..511
            // P tile: 64 rows(i) x 32 cols(j), transpose into Ps[k][i]
            int r  = idx >> 3;             // i 0..63
            int c4 = idx & 7;              // j/4 0..7
            float4 v = *reinterpret_cast<const float4*>(
                &attn[pbase + (size_t)r * SEQ + k0 + c4 * 4]);
            Ps[c4 * 4 + 0][r] = v.x; Ps[c4 * 4 + 1][r] = v.y;
            Ps[c4 * 4 + 2][r] = v.z; Ps[c4 * 4 + 3][r] = v.w;
            // V tile: 32 rows(j) x 64 cols(d)
            int vr  = idx >> 4;            // j 0..31
            int vc4 = idx & 15;            // d/4 0..15
            float4 w = *reinterpret_cast<const float4*>(
                &qkv[vbase + (size_t)(k0 + vr) * QKV_N + vc4 * 4]);
            *reinterpret_cast<float4*>(&Vs[vr][vc4 * 4]) = w;
        }
        __syncthreads();

        #pragma unroll
        for (int k = 0; k < 32; k++) {
            float rp[4], rv[4];
            #pragma unroll
            for (int m = 0; m < 4; m++) rp[m] = Ps[k][ty * 4 + m];
            #pragma unroll
            for (int n = 0; n < 4; n++) rv[n] = Vs[k][tx * 4 + n];
            #pragma unroll
            for (int m = 0; m < 4; m++)
                #pragma unroll
                for (int n = 0; n < 4; n++)
                    acc[m][n] = fmaf(rp[m], rv[n], acc[m][n]);
        }
        __syncthreads();
    }

    #pragma unroll
    for (int m = 0; m < 4; m++) {
        int i = i0 + ty * 4 + m;
        float4 v;
        v.x = acc[m][0]; v.y = acc[m][1]; v.z = acc[m][2]; v.w = acc[m][3];
        *reinterpret_cast<float4*>(
            &out[(size_t)(b * SEQ + i) * INNER + h * DH + tx * 4]) = v;
    }
}

// ---------------------------------------------------------------------------
extern "C" void kernel_launch(void* const* d_in, const int* in_sizes, int n_in,
                              void* d_out, int out_size)
{
    const float* x        = (const float*)d_in[0];
    const float* w_qkv    = (const float*)d_in[1];
    const float* reattn_w = (const float*)d_in[2];
    const float* ln_gamma = (const float*)d_in[3];
    const float* ln_beta  = (const float*)d_in[4];
    const float* w_out    = (const float*)d_in[5];
    const float* b_out    = (const float*)d_in[6];
    float* out = (float*)d_out;

    float *qkv = nullptr, *dots = nullptr, *av = nullptr;
    cudaGetSymbolAddress((void**)&qkv,  g_qkv);
    cudaGetSymbolAddress((void**)&dots, g_dots);
    cudaGetSymbolAddress((void**)&av,   g_av);

    dim3 blk(256);

    // 1) QKV projection: [4096,1024] @ [1024,3072]
    sgemm_kernel<false><<<dim3(QKV_N / 128, NTOK / 128), blk>>>(
        x, w_qkv, nullptr, qkv, NTOK, QKV_N, DMODEL);

    // 2) dots = scale * Q K^T per (b,h)
    dots_kernel<<<dim3(SEQ / 64, SEQ / 64, BATCH * HEADS), blk>>>(qkv, dots);

    // 3) fused softmax + re-attention head mix + LayerNorm (in place)
    softmax_mix_ln_kernel<<<BATCH * SEQ, blk>>>(dots, reattn_w, ln_gamma, ln_beta);

    // 4) AV -> [tok, inner] layout
    av_kernel<<<dim3(SEQ / 64, BATCH * HEADS), blk>>>(dots, qkv, av);

    // 5) output projection + bias: [4096,1024] @ [1024,1024]
    sgemm_kernel<true><<<dim3(DMODEL / 128, NTOK / 128), blk>>>(
        av, w_out, b_out, out, NTOK, DMODEL, DMODEL);
}

// round 2
// speedup vs baseline: 2.1653x; 2.1653x over previous
#include <cuda_runtime.h>
#include <stdint.h>
#include <math.h>

#define HEADS 16
#define DH    64
#define BATCH 8
#define SEQ   512
#define DMODEL 1024
#define INNER 1024            // HEADS*DH
#define QKV_N 3072            // 3*INNER
#define NTOK  4096            // BATCH*SEQ

// Scratch (device globals: allocation-free, graph-capture safe)
__device__ float g_qkv[(size_t)NTOK * QKV_N];               // 48 MB  [tok, 3*inner]
__device__ float g_dots[(size_t)BATCH * HEADS * SEQ * SEQ]; // 128 MB [b,h,i,j]
__device__ float g_av[(size_t)NTOK * INNER];                // 16 MB  [tok, inner]

// ---------------------------------------------------------------------------
// tf32 helpers
// ---------------------------------------------------------------------------
__device__ __forceinline__ uint32_t f2tf32(float x) {
    uint32_t u;
    asm("cvt.rna.tf32.f32 %0, %1;" : "=r"(u) : "f"(x));
    return u;
}

__device__ __forceinline__ void mma8(float* c, const uint32_t* a, const uint32_t* b) {
    asm volatile(
        "mma.sync.aligned.m16n8k8.row.col.f32.tf32.tf32.f32 "
        "{%0,%1,%2,%3}, {%4,%5,%6,%7}, {%8,%9}, {%0,%1,%2,%3};"
        : "+f"(c[0]), "+f"(c[1]), "+f"(c[2]), "+f"(c[3])
        : "r"(a[0]), "r"(a[1]), "r"(a[2]), "r"(a[3]),
          "r"(b[0]), "r"(b[1]));
}

// ---------------------------------------------------------------------------
// Unified tf32 tensor-core GEMM.
// MODE 0: QKV  proj  C[4096,3072] = x[4096,1024] @ w_qkv[1024,3072]
// MODE 1: OUT  proj  C[4096,1024] = av[4096,1024] @ w_out[1024,1024] + bias
// MODE 2: AV         per bh: C[512,64] = attn[512,512] @ V[512,64]
// MODE 3: DOTS       per bh: C[512,512] = 0.125 * Q[512,64] @ K[512,64]^T
//
// Block: 256 threads (8 warps, 4(M) x 2(N)), tile BM x BN, BK=32.
// A smem: [BM][36] (m-major, conflict-free frag reads: 4g+t distinct banks)
// B smem: MODE!=3: [32][BN+4] (k-major);  MODE==3: [BN][36] (n-major, K rows)
// ---------------------------------------------------------------------------
template<int MODE, int BM, int BN, int KTOT>
__global__ void __launch_bounds__(256) mma_gemm(
    const float* __restrict__ gA, const float* __restrict__ gB,
    const float* __restrict__ bias, float* __restrict__ gC)
{
    constexpr int MI = BM / 64;          // m16 tiles per warp (BM=128 -> 2)
    constexpr int NI = BN / 16;          // n8 tiles per warp
    constexpr int LDB_S = BN + 4;
    constexpr int BSZ = (MODE == 3) ? BN * 36 : 32 * LDB_S;

    __shared__ uint32_t sA[BM * 36];
    __shared__ uint32_t sB[BSZ];

    const int tid  = threadIdx.x;
    const int row0 = blockIdx.y * BM;
    const int col0 = blockIdx.x * BN;

    const float* A;
    const float* B;
    float* C;
    size_t lda, ldb, ldc;
    float alpha = 1.0f;

    if (MODE == 0) {
        A = gA; lda = DMODEL; B = gB; ldb = QKV_N; C = gC; ldc = QKV_N;
    } else if (MODE == 1) {
        A = gA; lda = DMODEL; B = gB; ldb = DMODEL; C = gC; ldc = DMODEL;
    } else if (MODE == 2) {
        const int bh = blockIdx.z, b = bh >> 4, h = bh & 15;
        A = gA + (size_t)bh * SEQ * SEQ;                          lda = SEQ;
        B = gB + (size_t)b * SEQ * QKV_N + 2 * INNER + (size_t)h * DH; ldb = QKV_N;
        C = gC + (size_t)b * SEQ * INNER + (size_t)h * DH;        ldc = INNER;
    } else {
        const int bh = blockIdx.z, b = bh >> 4, h = bh & 15;
        A = gA + (size_t)b * SEQ * QKV_N + (size_t)h * DH;        lda = QKV_N;
        B = gB + (size_t)b * SEQ * QKV_N + INNER + (size_t)h * DH; ldb = QKV_N;
        C = gC + (size_t)bh * SEQ * SEQ;                          ldc = SEQ;
        alpha = 0.125f;
    }

    const int warp = tid >> 5, lane = tid & 31;
    const int wm = warp >> 1, wn = warp & 1;
    const int g = lane >> 2, t4 = lane & 3;

    float acc[MI][NI][4] = {};

    for (int k0 = 0; k0 < KTOT; k0 += 32) {
        // ---- load A tile [BM x 32] ----
        #pragma unroll
        for (int t = 0; t < BM * 8 / 256; t++) {
            int idx = tid + t * 256;
            int r = idx >> 3, c4 = idx & 7;
            float4 v = *reinterpret_cast<const float4*>(
                &A[(size_t)(row0 + r) * lda + k0 + c4 * 4]);
            uint4 u;
            u.x = f2tf32(v.x); u.y = f2tf32(v.y);
            u.z = f2tf32(v.z); u.w = f2tf32(v.w);
            *reinterpret_cast<uint4*>(&sA[r * 36 + c4 * 4]) = u;
        }
        // ---- load B tile ----
        if (MODE == 3) {
            // Ks[n][k]: rows are K tokens (col0 + r), contiguous d
            #pragma unroll
            for (int t = 0; t < BN * 8 / 256; t++) {
                int idx = tid + t * 256;
                int r = idx >> 3, c4 = idx & 7;
                float4 v = *reinterpret_cast<const float4*>(
                    &B[(size_t)(col0 + r) * ldb + k0 + c4 * 4]);
                uint4 u;
                u.x = f2tf32(v.x); u.y = f2tf32(v.y);
                u.z = f2tf32(v.z); u.w = f2tf32(v.w);
                *reinterpret_cast<uint4*>(&sB[r * 36 + c4 * 4]) = u;
            }
        } else {
            constexpr int C4 = BN / 4;
            #pragma unroll
            for (int t = 0; t < 32 * C4 / 256; t++) {
                int idx = tid + t * 256;
                int r = idx / C4, c = idx % C4;
                float4 v = *reinterpret_cast<const float4*>(
                    &B[(size_t)(k0 + r) * ldb + col0 + c * 4]);
                uint4 u;
                u.x = f2tf32(v.x); u.y = f2tf32(v.y);
                u.z = f2tf32(v.z); u.w = f2tf32(v.w);
                *reinterpret_cast<uint4*>(&sB[r * LDB_S + c * 4]) = u;
            }
        }
        __syncthreads();

        // ---- 4 mma k-steps of 8 ----
        #pragma unroll
        for (int kk = 0; kk < 4; kk++) {
            const int k = kk * 8;
            uint32_t af[MI][4];
            #pragma unroll
            for (int mi = 0; mi < MI; mi++) {
                int r = wm * (BM / 4) + mi * 16 + g;
                af[mi][0] = sA[r * 36 + k + t4];
                af[mi][1] = sA[(r + 8) * 36 + k + t4];
                af[mi][2] = sA[r * 36 + k + 4 + t4];
                af[mi][3] = sA[(r + 8) * 36 + k + 4 + t4];
            }
            uint32_t bf[NI][2];
            #pragma unroll
            for (int ni = 0; ni < NI; ni++) {
                int c = wn * (BN / 2) + ni * 8 + g;
                if (MODE == 3) {
                    bf[ni][0] = sB[c * 36 + k + t4];
                    bf[ni][1] = sB[c * 36 + k + 4 + t4];
                } else {
                    bf[ni][0] = sB[(k + t4) * LDB_S + c];
                    bf[ni][1] = sB[(k + 4 + t4) * LDB_S + c];
                }
            }
            #pragma unroll
            for (int mi = 0; mi < MI; mi++)
                #pragma unroll
                for (int ni = 0; ni < NI; ni++)
                    mma8(acc[mi][ni], af[mi], bf[ni]);
        }
        __syncthreads();
    }

    // ---- epilogue ----
    #pragma unroll
    for (int mi = 0; mi < MI; mi++) {
        int r = row0 + wm * (BM / 4) + mi * 16 + g;
        #pragma unroll
        for (int ni = 0; ni < NI; ni++) {
            int c = col0 + wn * (BN / 2) + ni * 8 + 2 * t4;
            float b0 = 0.f, b1 = 0.f;
            if (MODE == 1) { b0 = bias[c]; b1 = bias[c + 1]; }
            float2 v0, v1;
            v0.x = acc[mi][ni][0] * alpha + b0;
            v0.y = acc[mi][ni][1] * alpha + b1;
            v1.x = acc[mi][ni][2] * alpha + b0;
            v1.y = acc[mi][ni][3] * alpha + b1;
            *reinterpret_cast<float2*>(&C[(size_t)r * ldc + c]) = v0;
            *reinterpret_cast<float2*>(&C[(size_t)(r + 8) * ldc + c]) = v1;
        }
    }
}

// ---------------------------------------------------------------------------
// Fused: per (b,i) — softmax over j per head, 16x16 head mix, LayerNorm over
// heads, gamma/beta. In-place on g_dots.
// ---------------------------------------------------------------------------
__global__ void __launch_bounds__(256) softmax_mix_ln_kernel(
    float* __restrict__ dots, const float* __restrict__ W,
    const float* __restrict__ gamma, const float* __restrict__ beta)
{
    const int bi = blockIdx.x;
    const int b  = bi >> 9;
    const int i  = bi & 511;

    __shared__ float sc[HEADS][SEQ];
    __shared__ float wmat[HEADS][HEADS];
    __shared__ float sg[HEADS], sb[HEADS];

    const int tid = threadIdx.x;
    wmat[tid >> 4][tid & 15] = W[tid];
    if (tid < HEADS) { sg[tid] = gamma[tid]; sb[tid] = beta[tid]; }

    #pragma unroll
    for (int t = 0; t < 8; t++) {
        int idx = tid + t * 256;
        int h   = idx >> 7;
        int j4  = idx & 127;
        float4 v = *reinterpret_cast<const float4*>(
            &dots[((size_t)(b * HEADS + h) * SEQ + i) * SEQ + j4 * 4]);
        *reinterpret_cast<float4*>(&sc[h][j4 * 4]) = v;
    }
    __syncthreads();

    const int warp = tid >> 5, lane = tid & 31;
    #pragma unroll
    for (int hh = 0; hh < 2; hh++) {
        int h = warp * 2 + hh;
        float mx = -1e30f;
        for (int j = lane; j < SEQ; j += 32) mx = fmaxf(mx, sc[h][j]);
        #pragma unroll
        for (int o = 16; o > 0; o >>= 1)
            mx = fmaxf(mx, __shfl_xor_sync(0xffffffffu, mx, o));
        float s = 0.f;
        for (int j = lane; j < SEQ; j += 32) {
            float e = __expf(sc[h][j] - mx);
            sc[h][j] = e;
            s += e;
        }
        #pragma unroll
        for (int o = 16; o > 0; o >>= 1)
            s += __shfl_xor_sync(0xffffffffu, s, o);
        float inv = 1.f / s;
        for (int j = lane; j < SEQ; j += 32) sc[h][j] *= inv;
    }
    __syncthreads();

    for (int j = tid; j < SEQ; j += 256) {
        float a[HEADS];
        #pragma unroll
        for (int h = 0; h < HEADS; h++) a[h] = sc[h][j];
        float mixed[HEADS];
        #pragma unroll
        for (int gg = 0; gg < HEADS; gg++) {
            float s = 0.f;
            #pragma unroll
            for (int h = 0; h < HEADS; h++) s = fmaf(a[h], wmat[h][gg], s);
            mixed[gg] = s;
        }
        float mean = 0.f;
        #pragma unroll
        for (int gg = 0; gg < HEADS; gg++) mean += mixed[gg];
        mean *= (1.f / HEADS);
        float var = 0.f;
        #pragma unroll
        for (int gg = 0; gg < HEADS; gg++) {
            float d = mixed[gg] - mean;
            var = fmaf(d, d, var);
        }
        var *= (1.f / HEADS);
        float inv = rsqrtf(var + 1e-3f);
        #pragma unroll
        for (int gg = 0; gg < HEADS; gg++) {
            float y = (mixed[gg] - mean) * inv * sg[gg] + sb[gg];
            dots[((size_t)(b * HEADS + gg) * SEQ + i) * SEQ + j] = y;
        }
    }
}

// ---------------------------------------------------------------------------
extern "C" void kernel_launch(void* const* d_in, const int* in_sizes, int n_in,
                              void* d_out, int out_size)
{
    const float* x        = (const float*)d_in[0];
    const float* w_qkv    = (const float*)d_in[1];
    const float* reattn_w = (const float*)d_in[2];
    const float* ln_gamma = (const float*)d_in[3];
    const float* ln_beta  = (const float*)d_in[4];
    const float* w_out    = (const float*)d_in[5];
    const float* b_out    = (const float*)d_in[6];
    float* out = (float*)d_out;

    float *qkv = nullptr, *dots = nullptr, *av = nullptr;
    cudaGetSymbolAddress((void**)&qkv,  g_qkv);
    cudaGetSymbolAddress((void**)&dots, g_dots);
    cudaGetSymbolAddress((void**)&av,   g_av);

    dim3 blk(256);

    // 1) QKV projection
    mma_gemm<0, 128, 128, 1024><<<dim3(QKV_N / 128, NTOK / 128), blk>>>(
        x, w_qkv, nullptr, qkv);

    // 2) dots = 0.125 * Q K^T per (b,h)
    mma_gemm<3, 128, 128, 64><<<dim3(SEQ / 128, SEQ / 128, BATCH * HEADS), blk>>>(
        qkv, qkv, nullptr, dots);

    // 3) fused softmax + head mix + LayerNorm (in place)
    softmax_mix_ln_kernel<<<BATCH * SEQ, blk>>>(dots, reattn_w, ln_gamma, ln_beta);

    // 4) AV
    mma_gemm<2, 128, 64, 512><<<dim3(1, SEQ / 128, BATCH * HEADS), blk>>>(
        dots, qkv, nullptr, av);

    // 5) output projection + bias
    mma_gemm<1, 128, 128, 1024><<<dim3(DMODEL / 128, NTOK / 128), blk>>>(
        av, w_out, b_out, out);
}

// round 3
// speedup vs baseline: 2.3226x; 1.0726x over previous
#include <cuda_runtime.h>
#include <stdint.h>
#include <math.h>

#define HEADS 16
#define DH    64
#define BATCH 8
#define SEQ   512
#define DMODEL 1024
#define INNER 1024            // HEADS*DH
#define QKV_N 3072            // 3*INNER
#define NTOK  4096            // BATCH*SEQ

// Scratch (device globals: allocation-free, graph-capture safe)
__device__ float g_qkv[(size_t)NTOK * QKV_N];               // 48 MB
__device__ float g_dots[(size_t)BATCH * HEADS * SEQ * SEQ]; // 128 MB
__device__ float g_av[(size_t)NTOK * INNER];                // 16 MB

// ---------------------------------------------------------------------------
__device__ __forceinline__ uint32_t f2tf32(float x) {
    uint32_t u;
    asm("cvt.rna.tf32.f32 %0, %1;" : "=r"(u) : "f"(x));
    return u;
}

__device__ __forceinline__ void mma8(float* c, const uint32_t* a, const uint32_t* b) {
    asm volatile(
        "mma.sync.aligned.m16n8k8.row.col.f32.tf32.tf32.f32 "
        "{%0,%1,%2,%3}, {%4,%5,%6,%7}, {%8,%9}, {%0,%1,%2,%3};"
        : "+f"(c[0]), "+f"(c[1]), "+f"(c[2]), "+f"(c[3])
        : "r"(a[0]), "r"(a[1]), "r"(a[2]), "r"(a[3]),
          "r"(b[0]), "r"(b[1]));
}

// ---------------------------------------------------------------------------
// Unified tf32 tensor-core GEMM with register-staged double buffering.
// MODE 0: QKV proj   MODE 1: OUT proj (+bias)
// MODE 2: AV (per bh)  MODE 3: DOTS (per bh, alpha=0.125, B n-major)
// 256 threads (8 warps 4x2), BM x BN tile, BK=32.
// ---------------------------------------------------------------------------
template<int MODE, int BM, int BN, int KTOT>
__global__ void __launch_bounds__(256) mma_gemm(
    const float* __restrict__ gA, const float* __restrict__ gB,
    const float* __restrict__ bias, float* __restrict__ gC)
{
    constexpr int MI = BM / 64;
    constexpr int NI = BN / 16;
    constexpr int LDB_S = BN + 4;
    constexpr int BSZ = (MODE == 3) ? BN * 36 : 32 * LDB_S;
    constexpr int NLDA = BM / 32;   // float4 per thread for A tile (BM x 32)
    constexpr int NLDB = BN / 32;   // float4 per thread for B tile

    __shared__ uint32_t sA[BM * 36];
    __shared__ uint32_t sB[BSZ];

    const int tid  = threadIdx.x;
    const int row0 = blockIdx.y * BM;
    const int col0 = blockIdx.x * BN;

    const float* A;
    const float* B;
    float* C;
    size_t lda, ldb, ldc;
    float alpha = 1.0f;

    if (MODE == 0) {
        A = gA; lda = DMODEL; B = gB; ldb = QKV_N; C = gC; ldc = QKV_N;
    } else if (MODE == 1) {
        A = gA; lda = DMODEL; B = gB; ldb = DMODEL; C = gC; ldc = DMODEL;
    } else if (MODE == 2) {
        const int bh = blockIdx.z, b = bh >> 4, h = bh & 15;
        A = gA + (size_t)bh * SEQ * SEQ;                               lda = SEQ;
        B = gB + (size_t)b * SEQ * QKV_N + 2 * INNER + (size_t)h * DH; ldb = QKV_N;
        C = gC + (size_t)b * SEQ * INNER + (size_t)h * DH;             ldc = INNER;
    } else {
        const int bh = blockIdx.z, b = bh >> 4, h = bh & 15;
        A = gA + (size_t)b * SEQ * QKV_N + (size_t)h * DH;             lda = QKV_N;
        B = gB + (size_t)b * SEQ * QKV_N + INNER + (size_t)h * DH;     ldb = QKV_N;
        C = gC + (size_t)bh * SEQ * SEQ;                               ldc = SEQ;
        alpha = 0.125f;
    }

    const int warp = tid >> 5, lane = tid & 31;
    const int wm = warp >> 1, wn = warp & 1;
    const int g = lane >> 2, t4 = lane & 3;

    // A-load geometry (BM x 32 tile): 8 float4 per row
    const int aR  = tid >> 3;           // base row (stride 32 over NLDA)
    const int aC4 = tid & 7;
    // B-load geometry
    const int bRk = tid / (BN / 4);     // k-major: row within 32
    const int bCk = tid % (BN / 4);     // float4 col
    // MODE3 n-major geometry same as A

    float4 ra[NLDA], rb[NLDB];

    auto loadA = [&](int k0) {
        #pragma unroll
        for (int t = 0; t < NLDA; t++) {
            int r = aR + t * 32;
            ra[t] = *reinterpret_cast<const float4*>(
                &A[(size_t)(row0 + r) * lda + k0 + aC4 * 4]);
        }
    };
    auto stsA = [&]() {
        #pragma unroll
        for (int t = 0; t < NLDA; t++) {
            int r = aR + t * 32;
            uint4 u;
            u.x = f2tf32(ra[t].x); u.y = f2tf32(ra[t].y);
            u.z = f2tf32(ra[t].z); u.w = f2tf32(ra[t].w);
            *reinterpret_cast<uint4*>(&sA[r * 36 + aC4 * 4]) = u;
        }
    };
    auto loadB = [&](int k0) {
        if (MODE == 3) {
            #pragma unroll
            for (int t = 0; t < NLDB; t++) {
                int r = aR + t * 32;
                rb[t] = *reinterpret_cast<const float4*>(
                    &B[(size_t)(col0 + r) * ldb + k0 + aC4 * 4]);
            }
        } else {
            #pragma unroll
            for (int t = 0; t < NLDB; t++) {
                int r = bRk + t * (1024 / BN);   // rows advance by 256/(BN/4)
                rb[t] = *reinterpret_cast<const float4*>(
                    &B[(size_t)(k0 + r) * ldb + col0 + bCk * 4]);
            }
        }
    };
    auto stsB = [&]() {
        if (MODE == 3) {
            #pragma unroll
            for (int t = 0; t < NLDB; t++) {
                int r = aR + t * 32;
                uint4 u;
                u.x = f2tf32(rb[t].x); u.y = f2tf32(rb[t].y);
                u.z = f2tf32(rb[t].z); u.w = f2tf32(rb[t].w);
                *reinterpret_cast<uint4*>(&sB[r * 36 + aC4 * 4]) = u;
            }
        } else {
            #pragma unroll
            for (int t = 0; t < NLDB; t++) {
                int r = bRk + t * (1024 / BN);
                uint4 u;
                u.x = f2tf32(rb[t].x); u.y = f2tf32(rb[t].y);
                u.z = f2tf32(rb[t].z); u.w = f2tf32(rb[t].w);
                *reinterpret_cast<uint4*>(&sB[r * LDB_S + bCk * 4]) = u;
            }
        }
    };

    float acc[MI][NI][4] = {};

    // Prologue: stage + commit tile 0
    loadA(0); loadB(0);
    stsA(); stsB();
    __syncthreads();

    for (int k0 = 0; k0 < KTOT; k0 += 32) {
        const bool more = (k0 + 32 < KTOT);
        if (more) { loadA(k0 + 32); loadB(k0 + 32); }   // LDG overlaps MMA below

        #pragma unroll
        for (int kk = 0; kk < 4; kk++) {
            const int k = kk * 8;
            uint32_t af[MI][4];
            #pragma unroll
            for (int mi = 0; mi < MI; mi++) {
                int r = wm * (BM / 4) + mi * 16 + g;
                af[mi][0] = sA[r * 36 + k + t4];
                af[mi][1] = sA[(r + 8) * 36 + k + t4];
                af[mi][2] = sA[r * 36 + k + 4 + t4];
                af[mi][3] = sA[(r + 8) * 36 + k + 4 + t4];
            }
            uint32_t bf[NI][2];
            #pragma unroll
            for (int ni = 0; ni < NI; ni++) {
                int c = wn * (BN / 2) + ni * 8 + g;
                if (MODE == 3) {
                    bf[ni][0] = sB[c * 36 + k + t4];
                    bf[ni][1] = sB[c * 36 + k + 4 + t4];
                } else {
                    bf[ni][0] = sB[(k + t4) * LDB_S + c];
                    bf[ni][1] = sB[(k + 4 + t4) * LDB_S + c];
                }
            }
            #pragma unroll
            for (int mi = 0; mi < MI; mi++)
                #pragma unroll
                for (int ni = 0; ni < NI; ni++)
                    mma8(acc[mi][ni], af[mi], bf[ni]);
        }

        if (more) {
            __syncthreads();
            stsA(); stsB();
            __syncthreads();
        }
    }

    // Epilogue
    #pragma unroll
    for (int mi = 0; mi < MI; mi++) {
        int r = row0 + wm * (BM / 4) + mi * 16 + g;
        #pragma unroll
        for (int ni = 0; ni < NI; ni++) {
            int c = col0 + wn * (BN / 2) + ni * 8 + 2 * t4;
            float b0 = 0.f, b1 = 0.f;
            if (MODE == 1) { b0 = bias[c]; b1 = bias[c + 1]; }
            float2 v0, v1;
            v0.x = acc[mi][ni][0] * alpha + b0;
            v0.y = acc[mi][ni][1] * alpha + b1;
            v1.x = acc[mi][ni][2] * alpha + b0;
            v1.y = acc[mi][ni][3] * alpha + b1;
            *reinterpret_cast<float2*>(&C[(size_t)r * ldc + c]) = v0;
            *reinterpret_cast<float2*>(&C[(size_t)(r + 8) * ldc + c]) = v1;
        }
    }
}

// ---------------------------------------------------------------------------
// Fused: per (b,i) — softmax over j per head, 16x16 head mix, LayerNorm over
// heads, gamma/beta. In-place on g_dots.
// ---------------------------------------------------------------------------
__global__ void __launch_bounds__(256) softmax_mix_ln_kernel(
    float* __restrict__ dots, const float* __restrict__ W,
    const float* __restrict__ gamma, const float* __restrict__ beta)
{
    const int bi = blockIdx.x;
    const int b  = bi >> 9;
    const int i  = bi & 511;

    __shared__ float sc[HEADS][SEQ];
    __shared__ float wmat[HEADS][HEADS];
    __shared__ float sg[HEADS], sb[HEADS];

    const int tid = threadIdx.x;
    wmat[tid >> 4][tid & 15] = W[tid];
    if (tid < HEADS) { sg[tid] = gamma[tid]; sb[tid] = beta[tid]; }

    #pragma unroll
    for (int t = 0; t < 8; t++) {
        int idx = tid + t * 256;
        int h   = idx >> 7;
        int j4  = idx & 127;
        float4 v = *reinterpret_cast<const float4*>(
            &dots[((size_t)(b * HEADS + h) * SEQ + i) * SEQ + j4 * 4]);
        *reinterpret_cast<float4*>(&sc[h][j4 * 4]) = v;
    }
    __syncthreads();

    const int warp = tid >> 5, lane = tid & 31;
    #pragma unroll
    for (int hh = 0; hh < 2; hh++) {
        int h = warp * 2 + hh;
        float mx = -1e30f;
        for (int j = lane; j < SEQ; j += 32) mx = fmaxf(mx, sc[h][j]);
        #pragma unroll
        for (int o = 16; o > 0; o >>= 1)
            mx = fmaxf(mx, __shfl_xor_sync(0xffffffffu, mx, o));
        float s = 0.f;
        for (int j = lane; j < SEQ; j += 32) {
            float e = __expf(sc[h][j] - mx);
            sc[h][j] = e;
            s += e;
        }
        #pragma unroll
        for (int o = 16; o > 0; o >>= 1)
            s += __shfl_xor_sync(0xffffffffu, s, o);
        float inv = 1.f / s;
        for (int j = lane; j < SEQ; j += 32) sc[h][j] *= inv;
    }
    __syncthreads();

    for (int j = tid; j < SEQ; j += 256) {
        float a[HEADS];
        #pragma unroll
        for (int h = 0; h < HEADS; h++) a[h] = sc[h][j];
        float mixed[HEADS];
        #pragma unroll
        for (int gg = 0; gg < HEADS; gg++) {
            float s = 0.f;
            #pragma unroll
            for (int h = 0; h < HEADS; h++) s = fmaf(a[h], wmat[h][gg], s);
            mixed[gg] = s;
        }
        float mean = 0.f;
        #pragma unroll
        for (int gg = 0; gg < HEADS; gg++) mean += mixed[gg];
        mean *= (1.f / HEADS);
        float var = 0.f;
        #pragma unroll
        for (int gg = 0; gg < HEADS; gg++) {
            float d = mixed[gg] - mean;
            var = fmaf(d, d, var);
        }
        var *= (1.f / HEADS);
        float inv = rsqrtf(var + 1e-3f);
        #pragma unroll
        for (int gg = 0; gg < HEADS; gg++) {
            float y = (mixed[gg] - mean) * inv * sg[gg] + sb[gg];
            dots[((size_t)(b * HEADS + gg) * SEQ + i) * SEQ + j] = y;
        }
    }
}

// ---------------------------------------------------------------------------
extern "C" void kernel_launch(void* const* d_in, const int* in_sizes, int n_in,
                              void* d_out, int out_size)
{
    const float* x        = (const float*)d_in[0];
    const float* w_qkv    = (const float*)d_in[1];
    const float* reattn_w = (const float*)d_in[2];
    const float* ln_gamma = (const float*)d_in[3];
    const float* ln_beta  = (const float*)d_in[4];
    const float* w_out    = (const float*)d_in[5];
    const float* b_out    = (const float*)d_in[6];
    float* out = (float*)d_out;

    float *qkv = nullptr, *dots = nullptr, *av = nullptr;
    cudaGetSymbolAddress((void**)&qkv,  g_qkv);
    cudaGetSymbolAddress((void**)&dots, g_dots);
    cudaGetSymbolAddress((void**)&av,   g_av);

    dim3 blk(256);

    // 1) QKV projection
    mma_gemm<0, 128, 128, 1024><<<dim3(QKV_N / 128, NTOK / 128), blk>>>(
        x, w_qkv, nullptr, qkv);

    // 2) dots = 0.125 * Q K^T per (b,h)
    mma_gemm<3, 128, 128, 64><<<dim3(SEQ / 128, SEQ / 128, BATCH * HEADS), blk>>>(
        qkv, qkv, nullptr, dots);

    // 3) fused softmax + head mix + LayerNorm (in place)
    softmax_mix_ln_kernel<<<BATCH * SEQ, blk>>>(dots, reattn_w, ln_gamma, ln_beta);

    // 4) AV
    mma_gemm<2, 128, 64, 512><<<dim3(1, SEQ / 128, BATCH * HEADS), blk>>>(
        dots, qkv, nullptr, av);

    // 5) output projection + bias
    mma_gemm<1, 128, 128, 1024><<<dim3(DMODEL / 128, NTOK / 128), blk>>>(
        av, w_out, b_out, out);
}